// round 13
// baseline (speedup 1.0000x reference)
#include <cuda_runtime.h>
#include <cstdint>

// Scratch: pre[row][32], row = b*512 + t, col = gate*8 + qubit. 33.5 MB.
__device__ float g_pre[512 * 512 * 32];

// ---------------------------------------------------------------------------
__device__ __forceinline__ unsigned long long ffma2(unsigned long long a,
                                                    unsigned long long b,
                                                    unsigned long long c) {
    unsigned long long d;
    asm("fma.rn.f32x2 %0, %1, %2, %3;" : "=l"(d) : "l"(a), "l"(b), "l"(c));
    return d;
}
__device__ __forceinline__ float ex2_approx(float x) {
    float y; asm("ex2.approx.f32 %0, %1;" : "=f"(y) : "f"(x)); return y;
}
__device__ __forceinline__ float rcp_approx(float x) {
    float y; asm("rcp.approx.f32 %0, %1;" : "=f"(y) : "f"(x)); return y;
}

// ---------------------------------------------------------------------------
// Kernel 1: pre[r][c] = sum_k X[r][k]*W[c][k] + bias[c] + theta[c]
//   M=262144, K=256, N=32. Block: 256 thr, 256 rows x 32 cols.
//   occupancy 3 (85 regs -- the occ-4/64-reg version spilled in the hot loop).
//   W master non-duplicated (32 KB); 8x32 (w,w)-pair slice re-staged per k-tile
//   into a 4 KB double buffer. Total smem 53.4 KB -> 3 blocks/SM.
// ---------------------------------------------------------------------------
constexpr int KT  = 8;      // k-tile
constexpr int XSg = 258;    // smem X row stride (floats): 256 rows + pad
// smem floats: master W 8192 | X 2*8*258 = 4128 | dupW 2*8*32 float2 = 1024
constexpr int SMEM_G = (8192 + 4128 + 1024) * 4;   // 53376 B

__global__ void __launch_bounds__(256, 3) gemm_kernel(
    const float* __restrict__ X,
    const float* __restrict__ Wf, const float* __restrict__ bf,
    const float* __restrict__ Wi, const float* __restrict__ bi,
    const float* __restrict__ Wg, const float* __restrict__ bg,
    const float* __restrict__ Wo, const float* __restrict__ bo,
    const float* __restrict__ th)
{
    extern __shared__ float sm[];
    float*  sW  = sm;                                   // [256][32] master
    float*  sX  = sm + 8192;                            // [2][KT][XSg]
    float2* sWD = reinterpret_cast<float2*>(sm + 8192 + 4128); // [2][KT][32]

    const int tid = threadIdx.x;

    // Load master W (row stride 264; first 256 entries = input part).
#pragma unroll
    for (int gi = 0; gi < 4; gi++) {
        const float* Wp = (gi == 0) ? Wf : (gi == 1) ? Wi : (gi == 2) ? Wg : Wo;
        for (int idx = tid; idx < 2048; idx += 256) {
            int k = idx >> 3, nn = idx & 7;
            sW[k * 32 + gi * 8 + nn] = Wp[nn * 264 + k];
        }
    }

    const size_t base0 = (size_t)blockIdx.x * 256;
    const int cg = tid >> 6;      // gate / col group, uniform per warp
    const int rp = tid & 63;      // row-pair id: rows 2rp,2rp+1 (+128)
    const int rq = tid & 127;     // staging row
    const int kc = tid >> 7;      // staging k chunk (0 -> k0..3, 1 -> k4..7)
    const int dk = tid >> 5;      // dup-stage k (0..7)
    const int dc = tid & 31;      // dup-stage col

    float4 ldv[2];
#pragma unroll
    for (int i = 0; i < 2; i++)
        ldv[i] = *reinterpret_cast<const float4*>(
            X + (base0 + rq + 128 * i) * 256 + kc * 4);

    unsigned long long acc[2][8];
#pragma unroll
    for (int j = 0; j < 2; j++)
#pragma unroll
        for (int c = 0; c < 8; c++) acc[j][c] = 0ull;

    // Stage X tile 0 into buffer 0.
#pragma unroll
    for (int i = 0; i < 2; i++) {
        float* dst = sX + kc * 4 * XSg + rq + 128 * i;
        dst[0 * XSg] = ldv[i].x; dst[1 * XSg] = ldv[i].y;
        dst[2 * XSg] = ldv[i].z; dst[3 * XSg] = ldv[i].w;
    }
    __syncthreads();                       // W master + X tile 0 visible

    // Stage dup-W tile 0 into buffer 0.
    {
        float w = sW[dk * 32 + dc];
        sWD[dk * 32 + dc] = make_float2(w, w);
    }
    __syncthreads();                       // dup-W tile 0 visible

    for (int kt = 0; kt < 32; kt++) {
        const int cur = kt & 1, nxt = (kt + 1) & 1;
        if (kt < 31) {
#pragma unroll
            for (int i = 0; i < 2; i++)
                ldv[i] = *reinterpret_cast<const float4*>(
                    X + (base0 + rq + 128 * i) * 256 + (kt + 1) * KT + kc * 4);
            // stage next dup-W slice (reads stable master, writes other buffer)
            float w = sW[((kt + 1) * KT + dk) * 32 + dc];
            sWD[nxt * (KT * 32) + dk * 32 + dc] = make_float2(w, w);
        }

        const float*  bx = sX + cur * (KT * XSg);
        const float2* wk = sWD + cur * (KT * 32) + cg * 8;
#pragma unroll
        for (int kk = 0; kk < KT; kk++) {
            unsigned long long xA = *reinterpret_cast<const unsigned long long*>(
                bx + kk * XSg + 2 * rp);
            unsigned long long xB = *reinterpret_cast<const unsigned long long*>(
                bx + kk * XSg + 2 * rp + 128);
            const ulonglong2* w2 = reinterpret_cast<const ulonglong2*>(wk + kk * 32);
            {
                ulonglong2 wa = w2[0], wb = w2[1];
                acc[0][0] = ffma2(wa.x, xA, acc[0][0]);
                acc[1][0] = ffma2(wa.x, xB, acc[1][0]);
                acc[0][1] = ffma2(wa.y, xA, acc[0][1]);
                acc[1][1] = ffma2(wa.y, xB, acc[1][1]);
                acc[0][2] = ffma2(wb.x, xA, acc[0][2]);
                acc[1][2] = ffma2(wb.x, xB, acc[1][2]);
                acc[0][3] = ffma2(wb.y, xA, acc[0][3]);
                acc[1][3] = ffma2(wb.y, xB, acc[1][3]);
            }
            {
                ulonglong2 wc = w2[2], wd = w2[3];
                acc[0][4] = ffma2(wc.x, xA, acc[0][4]);
                acc[1][4] = ffma2(wc.x, xB, acc[1][4]);
                acc[0][5] = ffma2(wc.y, xA, acc[0][5]);
                acc[1][5] = ffma2(wc.y, xB, acc[1][5]);
                acc[0][6] = ffma2(wd.x, xA, acc[0][6]);
                acc[1][6] = ffma2(wd.x, xB, acc[1][6]);
                acc[0][7] = ffma2(wd.y, xA, acc[0][7]);
                acc[1][7] = ffma2(wd.y, xB, acc[1][7]);
            }
        }

        if (kt < 31) {
            float* dstb = sX + nxt * (KT * XSg);
#pragma unroll
            for (int i = 0; i < 2; i++) {
                float* dst = dstb + kc * 4 * XSg + rq + 128 * i;
                dst[0 * XSg] = ldv[i].x; dst[1 * XSg] = ldv[i].y;
                dst[2 * XSg] = ldv[i].z; dst[3 * XSg] = ldv[i].w;
            }
        }
        __syncthreads();
    }

    // Epilogue: + bias + theta, write 2 row-pairs x 8 cols.
    const float* bptr = (cg == 0) ? bf : (cg == 1) ? bi : (cg == 2) ? bg : bo;
    float bt[8];
#pragma unroll
    for (int c = 0; c < 8; c++) bt[c] = bptr[c] + th[cg * 8 + c];
#pragma unroll
    for (int j = 0; j < 2; j++) {
        size_t pr = base0 + 2 * rp + 128 * j;
        float o0[8], o1[8];
#pragma unroll
        for (int c = 0; c < 8; c++) {
            float2 av = *reinterpret_cast<float2*>(&acc[j][c]);
            o0[c] = av.x + bt[c];
            o1[c] = av.y + bt[c];
        }
        float4* p0 = reinterpret_cast<float4*>(g_pre + pr * 32 + cg * 8);
        float4* p1 = reinterpret_cast<float4*>(g_pre + (pr + 1) * 32 + cg * 8);
        p0[0] = make_float4(o0[0], o0[1], o0[2], o0[3]);
        p0[1] = make_float4(o0[4], o0[5], o0[6], o0[7]);
        p1[0] = make_float4(o1[0], o1[1], o1[2], o1[3]);
        p1[1] = make_float4(o1[4], o1[5], o1[6], o1[7]);
    }
}

// ---------------------------------------------------------------------------
// Kernel 2: LSTM recurrence. 4 warps/block, one batch per warp,
// lane = gate*8 + qubit. TWO exchanges per step (was three): after the cosine
// broadcast every lane reads ALL 32 cosines (8 broadcast LDS.128) and computes
// all four gates' products + activations for its own qubit locally, so the
// f/i/g/o gather exchange disappears from the serial chain.
//   m_k = prod_{j<=k} cos(ang_j) (k>=1),  m_0 = prod_{j=1..7} cos(ang_j)
// ---------------------------------------------------------------------------
__global__ void __launch_bounds__(128) recur_kernel(
    const float* __restrict__ Wf, const float* __restrict__ Wi,
    const float* __restrict__ Wg, const float* __restrict__ Wo,
    float* __restrict__ out)
{
    __shared__ __align__(16) float cbuf[4][2][32];  // cos-1 exchange
    __shared__ __align__(16) float hbuf[4][2][8];   // hx broadcast

    const int wid  = threadIdx.x >> 5;
    const int lane = threadIdx.x & 31;
    const int b    = blockIdx.x * 4 + wid;
    const int g    = lane >> 3;
    const int n    = lane & 7;
    const float L2E = 1.4426950408889634f;

    const float* Wsel = (g == 0) ? Wf : (g == 1) ? Wi : (g == 2) ? Wg : Wo;
    float wh[8];
#pragma unroll
    for (int h = 0; h < 8; h++) wh[h] = Wsel[n * 264 + 256 + h];

    // Product inclusion mask (per this lane's qubit n, same for all gates):
    // n==0 -> j in 1..7, else j in 0..n.
    float incm[8];
#pragma unroll
    for (int j = 0; j < 8; j++)
        incm[j] = ((n == 0) ? (j >= 1) : (j <= n)) ? 1.0f : 0.0f;

    float hxa[8];
#pragma unroll
    for (int h = 0; h < 8; h++) hxa[h] = 0.f;
    float cx = 0.f, hx = 0.f;

    const float* pb = g_pre + (size_t)b * 512 * 32 + lane;
    float* ob = out + (size_t)b * 512 * 8 + n;

    float p0 = __ldg(pb);
    float p1 = __ldg(pb + 32);
    for (int t = 0; t < 512; t++) {
        float p2 = __ldg(pb + ((t + 2) & 511) * 32);   // distance-2 prefetch
        const int pp = t & 1;
        float* cb = &cbuf[wid][pp][0];
        float* hb = &hbuf[wid][pp][0];

        // angle = pre + W_h . hx  (two parallel fma chains)
        float s1 = p0, s2 = 0.f;
        s1 = fmaf(wh[0], hxa[0], s1);  s2 = fmaf(wh[1], hxa[1], s2);
        s1 = fmaf(wh[2], hxa[2], s1);  s2 = fmaf(wh[3], hxa[3], s2);
        s1 = fmaf(wh[4], hxa[4], s1);  s2 = fmaf(wh[5], hxa[5], s2);
        s1 = fmaf(wh[6], hxa[6], s1);  s2 = fmaf(wh[7], hxa[7], s2);
        float ang = s1 + s2;

        float cm1 = __cosf(ang) - 1.0f;

        // Exchange 1: publish cos-1, read ALL 32 (8 broadcast LDS.128).
        cb[lane] = cm1;
        __syncwarp();
        float4 cA[2], cB[2], cC[2], cD[2];
        cA[0] = *reinterpret_cast<const float4*>(cb + 0);
        cA[1] = *reinterpret_cast<const float4*>(cb + 4);
        cB[0] = *reinterpret_cast<const float4*>(cb + 8);
        cB[1] = *reinterpret_cast<const float4*>(cb + 12);
        cC[0] = *reinterpret_cast<const float4*>(cb + 16);
        cC[1] = *reinterpret_cast<const float4*>(cb + 20);
        cD[0] = *reinterpret_cast<const float4*>(cb + 24);
        cD[1] = *reinterpret_cast<const float4*>(cb + 28);

        // Masked tree product per gate, all at this lane's qubit n.
        float mF, mI, mG, mO;
        {
            float v0 = fmaf(incm[0], cA[0].x, 1.f), v1 = fmaf(incm[1], cA[0].y, 1.f);
            float v2 = fmaf(incm[2], cA[0].z, 1.f), v3 = fmaf(incm[3], cA[0].w, 1.f);
            float v4 = fmaf(incm[4], cA[1].x, 1.f), v5 = fmaf(incm[5], cA[1].y, 1.f);
            float v6 = fmaf(incm[6], cA[1].z, 1.f), v7 = fmaf(incm[7], cA[1].w, 1.f);
            mF = ((v0 * v1) * (v2 * v3)) * ((v4 * v5) * (v6 * v7));
        }
        {
            float v0 = fmaf(incm[0], cB[0].x, 1.f), v1 = fmaf(incm[1], cB[0].y, 1.f);
            float v2 = fmaf(incm[2], cB[0].z, 1.f), v3 = fmaf(incm[3], cB[0].w, 1.f);
            float v4 = fmaf(incm[4], cB[1].x, 1.f), v5 = fmaf(incm[5], cB[1].y, 1.f);
            float v6 = fmaf(incm[6], cB[1].z, 1.f), v7 = fmaf(incm[7], cB[1].w, 1.f);
            mI = ((v0 * v1) * (v2 * v3)) * ((v4 * v5) * (v6 * v7));
        }
        {
            float v0 = fmaf(incm[0], cC[0].x, 1.f), v1 = fmaf(incm[1], cC[0].y, 1.f);
            float v2 = fmaf(incm[2], cC[0].z, 1.f), v3 = fmaf(incm[3], cC[0].w, 1.f);
            float v4 = fmaf(incm[4], cC[1].x, 1.f), v5 = fmaf(incm[5], cC[1].y, 1.f);
            float v6 = fmaf(incm[6], cC[1].z, 1.f), v7 = fmaf(incm[7], cC[1].w, 1.f);
            mG = ((v0 * v1) * (v2 * v3)) * ((v4 * v5) * (v6 * v7));
        }
        {
            float v0 = fmaf(incm[0], cD[0].x, 1.f), v1 = fmaf(incm[1], cD[0].y, 1.f);
            float v2 = fmaf(incm[2], cD[0].z, 1.f), v3 = fmaf(incm[3], cD[0].w, 1.f);
            float v4 = fmaf(incm[4], cD[1].x, 1.f), v5 = fmaf(incm[5], cD[1].y, 1.f);
            float v6 = fmaf(incm[6], cD[1].z, 1.f), v7 = fmaf(incm[7], cD[1].w, 1.f);
            mO = ((v0 * v1) * (v2 * v3)) * ((v4 * v5) * (v6 * v7));
        }

        // Activations (in-lane, all four gates): sigmoid for f,i,o; tanh for g.
        float fv = rcp_approx(1.0f + ex2_approx(mF * (-L2E)));
        float iv = rcp_approx(1.0f + ex2_approx(mI * (-L2E)));
        float gv = fmaf(2.0f, rcp_approx(1.0f + ex2_approx(mG * (-2.0f * L2E))), -1.0f);
        float ov = rcp_approx(1.0f + ex2_approx(mO * (-L2E)));

        cx = fmaf(fv, cx, iv * gv);

        // hx = ov * tanh(cx);  tanh(x) = 2*sigmoid(2x)-1
        float e2 = ex2_approx(cx * (-2.0f * L2E));
        float r2 = rcp_approx(1.0f + e2);
        hx = ov * fmaf(2.0f, r2, -1.0f);

        // Exchange 2: broadcast hx vector for next step's matvec.
        if (lane < 8) hb[lane] = hx;
        __syncwarp();
        float4 h0 = *reinterpret_cast<const float4*>(hb);
        float4 h1 = *reinterpret_cast<const float4*>(hb + 4);
        hxa[0] = h0.x; hxa[1] = h0.y; hxa[2] = h0.z; hxa[3] = h0.w;
        hxa[4] = h1.x; hxa[5] = h1.y; hxa[6] = h1.z; hxa[7] = h1.w;

        if (lane < 8) ob[t * 8] = hx;
        p0 = p1; p1 = p2;
    }

    if (lane < 8) {
        out[2097152 + b * 8 + n] = hx;           // final hx
        out[2097152 + 4096 + b * 8 + n] = cx;    // final cx
    }
}

// ---------------------------------------------------------------------------
extern "C" void kernel_launch(void* const* d_in, const int* in_sizes, int n_in,
                              void* d_out, int out_size) {
    const float* X  = (const float*)d_in[0];
    const float* Wf = (const float*)d_in[1];
    const float* bf = (const float*)d_in[2];
    const float* Wi = (const float*)d_in[3];
    const float* bi = (const float*)d_in[4];
    const float* Wg = (const float*)d_in[5];
    const float* bg = (const float*)d_in[6];
    const float* Wo = (const float*)d_in[7];
    const float* bo = (const float*)d_in[8];
    const float* th = (const float*)d_in[9];
    float* out = (float*)d_out;

    cudaFuncSetAttribute(gemm_kernel,
                         cudaFuncAttributeMaxDynamicSharedMemorySize, SMEM_G);

    gemm_kernel<<<1024, 256, SMEM_G>>>(X, Wf, bf, Wi, bi, Wg, bg, Wo, bo, th);
    recur_kernel<<<128, 128>>>(Wf, Wi, Wg, Wo, out);
}

// round 15
// speedup vs baseline: 1.8231x; 1.8231x over previous
#include <cuda_runtime.h>
#include <cuda_bf16.h>
#include <cstdint>

// Scratch: pre[row][32], row = b*512 + t, col = gate*8 + qubit. 33.5 MB.
__device__ float g_pre[512 * 512 * 32];

// ---------------------------------------------------------------------------
__device__ __forceinline__ float ex2_approx(float x) {
    float y; asm("ex2.approx.f32 %0, %1;" : "=f"(y) : "f"(x)); return y;
}
__device__ __forceinline__ float rcp_approx(float x) {
    float y; asm("rcp.approx.f32 %0, %1;" : "=f"(y) : "f"(x)); return y;
}

// mma.sync m16n8k16 row.col f32.bf16.bf16.f32 (portable HMMA, sm_80+ base PTX)
__device__ __forceinline__ void mma16816(float* d, const uint32_t* a,
                                         uint32_t b0, uint32_t b1) {
    asm volatile(
        "mma.sync.aligned.m16n8k16.row.col.f32.bf16.bf16.f32 "
        "{%0,%1,%2,%3}, {%4,%5,%6,%7}, {%8,%9}, {%0,%1,%2,%3};"
        : "+f"(d[0]), "+f"(d[1]), "+f"(d[2]), "+f"(d[3])
        : "r"(a[0]), "r"(a[1]), "r"(a[2]), "r"(a[3]), "r"(b0), "r"(b1));
}

__device__ __forceinline__ uint32_t bf2_bits(__nv_bfloat162 v) {
    return *reinterpret_cast<uint32_t*>(&v);
}

// ---------------------------------------------------------------------------
// Kernel 1 (HMMA): pre[r][c] = sum_k X[r][k]*W[c][k] + bias[c] + theta[c]
//   M=262144, K=256, N=32. Block: 256 thr / 8 warps, 128 rows; warp = 16 rows.
//   X, W split into bf16 hi+lo; 3 passes (hh+hl+lh) accumulated in fp32.
//   W staged in smem (hi/lo, col stride 264 bf16 -> conflict-free b-frag LDS).
// ---------------------------------------------------------------------------
constexpr int WST = 264;   // smem W col stride (bf16 elements)

__global__ void __launch_bounds__(256) gemm_hmma_kernel(
    const float* __restrict__ X,
    const float* __restrict__ Wf, const float* __restrict__ bf,
    const float* __restrict__ Wi, const float* __restrict__ bi,
    const float* __restrict__ Wg, const float* __restrict__ bg,
    const float* __restrict__ Wo, const float* __restrict__ bo,
    const float* __restrict__ th)
{
    __shared__ __nv_bfloat16 sWH[32 * WST];
    __shared__ __nv_bfloat16 sWL[32 * WST];
    __shared__ float sBT[32];

    const int tid = threadIdx.x;

    // Stage W hi/lo (W row stride 264; first 256 entries = input part).
    for (int idx = tid; idx < 8192; idx += 256) {
        int col = idx >> 8, k = idx & 255;
        const float* Wp = (col < 8) ? Wf : (col < 16) ? Wi : (col < 24) ? Wg : Wo;
        float w = Wp[(col & 7) * 264 + k];
        __nv_bfloat16 h = __float2bfloat16(w);
        float lo = w - __bfloat162float(h);
        sWH[col * WST + k] = h;
        sWL[col * WST + k] = __float2bfloat16(lo);
    }
    if (tid < 32) {
        const float* bp = (tid < 8) ? bf : (tid < 16) ? bi : (tid < 24) ? bg : bo;
        sBT[tid] = bp[tid & 7] + th[tid];
    }
    __syncthreads();

    const int w    = tid >> 5;
    const int lane = tid & 31;
    const int grp  = lane >> 2;     // 0..7 (fragment row / b-col)
    const int tig  = lane & 3;      // 0..3 (fragment k pair)

    const size_t row0 = (size_t)blockIdx.x * 128 + w * 16 + grp;
    const float* x0 = X + row0 * 256;
    const float* x1 = X + (row0 + 8) * 256;

    float d[4][4];
#pragma unroll
    for (int nt = 0; nt < 4; nt++)
#pragma unroll
        for (int i = 0; i < 4; i++) d[nt][i] = 0.f;

#pragma unroll 4
    for (int ks = 0; ks < 16; ks++) {
        const int kb = ks * 16 + tig * 2;

        // A fragment loads (canonical ldmatrix-x4 order):
        //   a0=(r,k) a1=(r+8,k) a2=(r,k+8) a3=(r+8,k+8)
        float2 v00 = *reinterpret_cast<const float2*>(x0 + kb);
        float2 v10 = *reinterpret_cast<const float2*>(x1 + kb);
        float2 v01 = *reinterpret_cast<const float2*>(x0 + kb + 8);
        float2 v11 = *reinterpret_cast<const float2*>(x1 + kb + 8);

        __nv_bfloat162 h00 = __floats2bfloat162_rn(v00.x, v00.y);
        __nv_bfloat162 h10 = __floats2bfloat162_rn(v10.x, v10.y);
        __nv_bfloat162 h01 = __floats2bfloat162_rn(v01.x, v01.y);
        __nv_bfloat162 h11 = __floats2bfloat162_rn(v11.x, v11.y);

        uint32_t ah[4] = {bf2_bits(h00), bf2_bits(h10), bf2_bits(h01), bf2_bits(h11)};

        __nv_bfloat162 l00 = __floats2bfloat162_rn(
            v00.x - __bfloat162float(h00.x), v00.y - __bfloat162float(h00.y));
        __nv_bfloat162 l10 = __floats2bfloat162_rn(
            v10.x - __bfloat162float(h10.x), v10.y - __bfloat162float(h10.y));
        __nv_bfloat162 l01 = __floats2bfloat162_rn(
            v01.x - __bfloat162float(h01.x), v01.y - __bfloat162float(h01.y));
        __nv_bfloat162 l11 = __floats2bfloat162_rn(
            v11.x - __bfloat162float(h11.x), v11.y - __bfloat162float(h11.y));

        uint32_t al[4] = {bf2_bits(l00), bf2_bits(l10), bf2_bits(l01), bf2_bits(l11)};

#pragma unroll
        for (int nt = 0; nt < 4; nt++) {
            const int bo = (nt * 8 + grp) * WST + kb;
            uint32_t bh0 = *reinterpret_cast<const uint32_t*>(sWH + bo);
            uint32_t bh1 = *reinterpret_cast<const uint32_t*>(sWH + bo + 8);
            uint32_t bl0 = *reinterpret_cast<const uint32_t*>(sWL + bo);
            uint32_t bl1 = *reinterpret_cast<const uint32_t*>(sWL + bo + 8);
            mma16816(d[nt], ah, bh0, bh1);   // hh
            mma16816(d[nt], ah, bl0, bl1);   // hl
            mma16816(d[nt], al, bh0, bh1);   // lh
        }
    }

    // Epilogue: + bias + theta.  D: d0,d1=(row grp, col tig*2,+1); d2,d3=(+8).
    float* dst0 = g_pre + row0 * 32;
    float* dst1 = g_pre + (row0 + 8) * 32;
#pragma unroll
    for (int nt = 0; nt < 4; nt++) {
        const int c = nt * 8 + tig * 2;
        float b0 = sBT[c], b1 = sBT[c + 1];
        *reinterpret_cast<float2*>(dst0 + c) =
            make_float2(d[nt][0] + b0, d[nt][1] + b1);
        *reinterpret_cast<float2*>(dst1 + c) =
            make_float2(d[nt][2] + b0, d[nt][3] + b1);
    }
}

// ---------------------------------------------------------------------------
// Kernel 2: LSTM recurrence (R11 version, empirically fastest at 167 us).
// 4 warps/block, one batch per warp, lane = gate*8 + qubit.
//   m_k = prod_{j<=k} cos(ang_j) (k>=1),  m_0 = prod_{j=1..7} cos(ang_j)
// ---------------------------------------------------------------------------
__global__ void __launch_bounds__(128) recur_kernel(
    const float* __restrict__ Wf, const float* __restrict__ Wi,
    const float* __restrict__ Wg, const float* __restrict__ Wo,
    float* __restrict__ out)
{
    const int wid  = threadIdx.x >> 5;
    const int lane = threadIdx.x & 31;
    const int b    = blockIdx.x * 4 + wid;
    const int g    = lane >> 3;
    const int n    = lane & 7;
    const int segb = g * 8;
    const unsigned FULL = 0xffffffffu;
    const float L2E = 1.4426950408889634f;

    const float* Wsel = (g == 0) ? Wf : (g == 1) ? Wi : (g == 2) ? Wg : Wo;
    float wh[8];
#pragma unroll
    for (int h = 0; h < 8; h++) wh[h] = Wsel[n * 264 + 256 + h];

    float incm[8];
#pragma unroll
    for (int j = 0; j < 8; j++)
        incm[j] = ((n == 0) ? (j >= 1) : (j <= n)) ? 1.0f : 0.0f;

    const float sA2 = (g == 2) ? (-2.0f * L2E) : (-L2E);
    const float am  = (g == 2) ? 2.0f : 1.0f;
    const float ab  = (g == 2) ? -1.0f : 0.0f;

    float hxa[8];
#pragma unroll
    for (int h = 0; h < 8; h++) hxa[h] = 0.f;
    float cx = 0.f, hx = 0.f;

    const float* pb = g_pre + (size_t)b * 512 * 32 + lane;
    float* ob = out + (size_t)b * 512 * 8 + n;

    float p0 = __ldg(pb);
    float p1 = __ldg(pb + 32);
    for (int t = 0; t < 512; t++) {
        float p2 = __ldg(pb + ((t + 2) & 511) * 32);

        float s1 = p0, s2 = 0.f;
        s1 = fmaf(wh[0], hxa[0], s1);  s2 = fmaf(wh[1], hxa[1], s2);
        s1 = fmaf(wh[2], hxa[2], s1);  s2 = fmaf(wh[3], hxa[3], s2);
        s1 = fmaf(wh[4], hxa[4], s1);  s2 = fmaf(wh[5], hxa[5], s2);
        s1 = fmaf(wh[6], hxa[6], s1);  s2 = fmaf(wh[7], hxa[7], s2);
        float ang = s1 + s2;

        float cm1 = __cosf(ang) - 1.0f;

        float vv[8];
#pragma unroll
        for (int j = 0; j < 8; j++) {
            float cj = __shfl_sync(FULL, cm1, segb + j);
            vv[j] = fmaf(incm[j], cj, 1.0f);
        }
        float m = ((vv[0] * vv[1]) * (vv[2] * vv[3])) *
                  ((vv[4] * vv[5]) * (vv[6] * vv[7]));

        float e = ex2_approx(m * sA2);
        float r = rcp_approx(1.0f + e);
        float a = fmaf(am, r, ab);

        float fv = __shfl_sync(FULL, a, n);
        float iv = __shfl_sync(FULL, a, n + 8);
        float gv = __shfl_sync(FULL, a, n + 16);
        float ov = __shfl_sync(FULL, a, n + 24);

        cx = fmaf(fv, cx, iv * gv);

        float e2 = ex2_approx(cx * (-2.0f * L2E));
        float r2 = rcp_approx(1.0f + e2);
        hx = ov * fmaf(2.0f, r2, -1.0f);

#pragma unroll
        for (int h = 0; h < 8; h++) hxa[h] = __shfl_sync(FULL, hx, h);

        if (lane < 8) ob[t * 8] = hx;
        p0 = p1; p1 = p2;
    }

    if (lane < 8) {
        out[2097152 + b * 8 + n] = hx;           // final hx
        out[2097152 + 4096 + b * 8 + n] = cx;    // final cx
    }
}

// ---------------------------------------------------------------------------
extern "C" void kernel_launch(void* const* d_in, const int* in_sizes, int n_in,
                              void* d_out, int out_size) {
    const float* X  = (const float*)d_in[0];
    const float* Wf = (const float*)d_in[1];
    const float* bf = (const float*)d_in[2];
    const float* Wi = (const float*)d_in[3];
    const float* bi = (const float*)d_in[4];
    const float* Wg = (const float*)d_in[5];
    const float* bg = (const float*)d_in[6];
    const float* Wo = (const float*)d_in[7];
    const float* bo = (const float*)d_in[8];
    const float* th = (const float*)d_in[9];
    float* out = (float*)d_out;

    gemm_hmma_kernel<<<2048, 256>>>(X, Wf, bf, Wi, bi, Wg, bg, Wo, bo, th);
    recur_kernel<<<128, 128>>>(Wf, Wi, Wg, Wo, out);
}